// round 14
// baseline (speedup 1.0000x reference)
#include <cuda_runtime.h>
#include <cuda_fp16.h>
#include <cuda.h>
#include <cstdint>

// ---------------------------------------------------------------------------
// Problem constants
// ---------------------------------------------------------------------------
constexpr int NROW = 8192;
constexpr int TOT  = 8192;
constexpr int ROWS_TOTAL = 131072;   // 8192*(1+3+5+7)

// ---------------------------------------------------------------------------
// Device scratch
// ---------------------------------------------------------------------------
__device__ __align__(128) __half g_xT[(size_t)ROWS_TOTAL * 512];   // fp16 x, K(u)-major
__device__ __align__(128) __half g_w[4 * 512 * 512];               // fp16 w, [seg][v][u]
__device__ int g_flagX[1024];                                      // per m-tile arrive counters

// ---------------------------------------------------------------------------
// PTX helpers (compute_103-safe: TMA tile / mbarrier / ldmatrix / mma.sync)
// ---------------------------------------------------------------------------
__device__ __forceinline__ uint32_t smem_u32(const void* p) {
    uint32_t a;
    asm("{ .reg .u64 t; cvta.to.shared.u64 t, %1; cvt.u32.u64 %0, t; }"
        : "=r"(a) : "l"(p));
    return a;
}
__device__ __forceinline__ uint32_t swz(uint32_t off) {        // SW128 pattern
    return off ^ ((off >> 3) & 0x70);
}
__device__ __forceinline__ void ldmx4(uint32_t* r, uint32_t addr) {
    asm volatile("ldmatrix.sync.aligned.m8n8.x4.shared.b16 {%0,%1,%2,%3}, [%4];"
        : "=r"(r[0]), "=r"(r[1]), "=r"(r[2]), "=r"(r[3]) : "r"(addr));
}
__device__ __forceinline__ void mma16816(float* c, const uint32_t* a,
                                         uint32_t b0, uint32_t b1) {
    asm volatile(
        "mma.sync.aligned.m16n8k16.row.col.f32.f16.f16.f32 "
        "{%0,%1,%2,%3}, {%4,%5,%6,%7}, {%8,%9}, {%0,%1,%2,%3};"
        : "+f"(c[0]), "+f"(c[1]), "+f"(c[2]), "+f"(c[3])
        : "r"(a[0]), "r"(a[1]), "r"(a[2]), "r"(a[3]), "r"(b0), "r"(b1));
}
__device__ __forceinline__ void mbar_init(uint32_t mbar, uint32_t cnt) {
    asm volatile("mbarrier.init.shared.b64 [%0], %1;" :: "r"(mbar), "r"(cnt) : "memory");
}
__device__ __forceinline__ void fence_proxy_async_cta() {
    asm volatile("fence.proxy.async.shared::cta;" ::: "memory");
}
__device__ __forceinline__ void mbar_expect_tx(uint32_t mbar, uint32_t bytes) {
    asm volatile("mbarrier.arrive.expect_tx.shared.b64 _, [%0], %1;"
                 :: "r"(mbar), "r"(bytes) : "memory");
}
__device__ __forceinline__ void mbar_arrive(uint32_t mbar) {
    asm volatile("mbarrier.arrive.shared.b64 _, [%0];" :: "r"(mbar) : "memory");
}
__device__ __forceinline__ void mbar_wait(uint32_t mbar, uint32_t parity) {
    asm volatile(
        "{\n\t.reg .pred P;\n"
        "W%=:\n\t"
        "mbarrier.try_wait.parity.acquire.cta.shared::cta.b64 P, [%0], %1, 0x989680;\n\t"
        "@!P bra W%=;\n\t}"
        :: "r"(mbar), "r"(parity) : "memory");
}
__device__ __forceinline__ void tma2d(uint32_t smem, const void* map,
                                      int c0, int c1, uint32_t mbar) {
    asm volatile(
        "cp.async.bulk.tensor.2d.shared::cta.global.tile.mbarrier::complete_tx::bytes "
        "[%0], [%1, {%2, %3}], [%4];"
        :: "r"(smem), "l"(map), "r"(c0), "r"(c1), "r"(mbar) : "memory");
}
__device__ __forceinline__ void flag_wait4(const int* p) {
    uint32_t v;
    do {
        asm volatile("ld.acquire.gpu.global.u32 %0, [%1];" : "=r"(v) : "l"(p) : "memory");
        if (v < 4) __nanosleep(128);
    } while (v < 4);
}

// ---------------------------------------------------------------------------
// prep_w: w -> fp16 transposed [v][u]; block 0 also resets the X-ready flags.
// ---------------------------------------------------------------------------
__global__ void __launch_bounds__(256)
prep_w(const float* __restrict__ w0, const float* __restrict__ w1,
       const float* __restrict__ w2, const float* __restrict__ w3)
{
    __shared__ float t[32][33];
    const int tid = threadIdx.x;
    if (blockIdx.x == 0)
        for (int i = tid; i < 1024; i += 256) g_flagX[i] = 0;

    const int bz = blockIdx.x >> 8, bx = blockIdx.x & 15, by = (blockIdx.x >> 4) & 15;
    const float* w = (bz == 0) ? w0 : (bz == 1) ? w1 : (bz == 2) ? w2 : w3;
    const int v0 = bx * 32, u0 = by * 32;
    const int tx = tid & 31, ty = tid >> 5;

    for (int uu = ty; uu < 32; uu += 8)
        t[uu][tx] = w[(size_t)(u0 + uu) * 512 + v0 + tx];
    __syncthreads();

    const size_t segb = (size_t)bz * 262144;
    for (int vv = ty; vv < 32; vv += 8)
        g_w[segb + (size_t)(v0 + vv) * 512 + u0 + tx] = __float2half_rn(t[tx][vv]);
}

// ---------------------------------------------------------------------------
// Prep body (dedicated CTAs): convert one QUARTER tile (32 m-rows) of x into
// g_xT, publish via atomic counter, retire.  (Validated in R13.)
// ---------------------------------------------------------------------------
constexpr int STAGE    = 32768;              // X 16K + W 16K
constexpr int MBAR_OFF = 3 * STAGE;          // 98304
constexpr int SMEM_DYN = MBAR_OFF + 48;      // + 3 full + 3 empty mbars

template<int SEG, int D, int OFF, int ROWBASE>
__device__ __forceinline__ void prep_body(const float* __restrict__ x, int lb4, char* sm)
{
    const int tid = threadIdx.x;
    const int mb  = (lb4 >> 2) * 128;
    const int q   = lb4 & 3;
    const int m0  = mb + q * 32;                   // [m0, m0+32)
    const int nA  = m0 / D;
    const int nB  = (m0 + 31) / D;
    const int cnt = nB - nA + 1;                   // <= 32 n-rows (D=1)
    float* sx = (float*)sm;                        // up to 86 KB used
    constexpr int SLAB = 512 * D;                  // floats per n

    const int nf4 = cnt * (SLAB / 4);
    for (int idx = tid; idx < nf4; idx += 256) {
        const int nl = idx / (SLAB / 4);
        const int r4 = idx - nl * (SLAB / 4);
        ((float4*)sx)[idx] =
            *(const float4*)(x + (size_t)(nA + nl) * TOT + OFF + r4 * 4);
    }
    __syncthreads();

    for (int e2 = tid; e2 < 32 * 256; e2 += 256) { // 32 rows x 256 half2
        const int mr = e2 >> 8;
        const int u2 = (e2 & 255) * 2;
        const int m  = m0 + mr;
        const int n  = m / D;                      // constexpr D: mul-shift
        const int i  = m - n * D;
        const float* s = sx + (n - nA) * SLAB;
        __half2 p;
        p.x = __float2half_rn(s[u2 * D + i]);
        p.y = __float2half_rn(s[(u2 + 1) * D + i]);
        *(__half2*)&g_xT[((size_t)ROWBASE + m) * 512 + u2] = p;
    }
    __threadfence();                               // publish (gpu scope)
    __syncthreads();
    if (tid == 0) atomicAdd(&g_flagX[ROWBASE / 128 + (lb4 >> 2)], 1);
}

// ---------------------------------------------------------------------------
// Main GEMM body (R11-validated): TMA 3-stage ring, no syncthreads in loop.
// tid 0 waits for its tile's 4 prep quarters before the first TMA.
// ---------------------------------------------------------------------------
template<int SEG, int D, int OFF, int ROWBASE>
__device__ __forceinline__ void gemm_body(float* __restrict__ out, int lb, char* sm,
                                          const CUtensorMap* tmX, const CUtensorMap* tmW)
{
    const int tid  = threadIdx.x;
    const int lane = tid & 31;
    const int wid  = tid >> 5;
    const int vb   = (lb & 3) * 128;       // v-tile base (fast -> L2 X reuse)
    const int mb   = (lb >> 2) * 128;      // m-tile base
    const int wm   = (wid & 1) * 64;       // warp M offset (2x4 warp grid)
    const int wn   = (wid >> 1) * 32;      // warp N offset
    const uint32_t smb = smem_u32(sm);
    const uint32_t mbF = smb + MBAR_OFF;       // full[3]
    const uint32_t mbE = smb + MBAR_OFF + 24;  // empty[3]
    const int* flag = &g_flagX[ROWBASE / 128 + (lb >> 2)];

    if (tid == 0) {
        #pragma unroll
        for (int b = 0; b < 3; ++b) {
            mbar_init(mbF + b * 8, 1);     // completed by expect_tx + TMA tx
            mbar_init(mbE + b * 8, 8);     // one arrive per warp
        }
        fence_proxy_async_cta();           // init visible to async (TMA) proxy
    }
    __syncthreads();

    // producer: chunk j -> buffer j%3.  empty parity: ((j/3)&1)^1 (first pass free)
    auto produce = [&](int j) {
        const int buf = j % 3;
        const uint32_t fm = mbF + buf * 8;
        mbar_wait(mbE + buf * 8, ((j / 3) & 1) ^ 1);
        mbar_expect_tx(fm, 2 * 16384);
        tma2d(smb + buf * STAGE,         tmX, j * 64, ROWBASE + mb,  fm);
        tma2d(smb + buf * STAGE + 16384, tmW, j * 64, SEG * 512 + vb, fm);
    };

    float acc[4][4][4] = {};

    // ldmatrix lane addressing (swizzle computed per-ks: swz does NOT
    // distribute over +ks*32 when the XOR pattern occupies bits 5-6!)
    const int a_m  = (lane & 7) + ((lane >> 3) & 1) * 8;
    const int a_kb = ((lane >> 4) & 1) * 16;
    const int b_n  = (lane & 7) + ((lane >> 4) & 1) * 8;
    const int b_kb = ((lane >> 3) & 1) * 16;
    const uint32_t aBase = (uint32_t)((wm + a_m) * 128 + a_kb);
    const uint32_t bBase = (uint32_t)((wn + b_n) * 128 + b_kb);

    auto compute = [&](int buf) {
        const uint32_t baseX = smb + buf * STAGE;
        const uint32_t baseW = baseX + 16384;
        #pragma unroll
        for (int ks = 0; ks < 4; ++ks) {
            uint32_t a[4][4], b[2][4];
            const uint32_t aA = baseX + swz(aBase + ks * 32);
            const uint32_t bA = baseW + swz(bBase + ks * 32);
            #pragma unroll
            for (int mk = 0; mk < 4; ++mk) ldmx4(a[mk], aA + mk * 2048);
            #pragma unroll
            for (int nh = 0; nh < 2; ++nh) ldmx4(b[nh], bA + nh * 2048);
            #pragma unroll
            for (int mk = 0; mk < 4; ++mk)
                #pragma unroll
                for (int nb = 0; nb < 4; ++nb)
                    mma16816(acc[mk][nb], a[mk],
                             b[nb >> 1][(nb & 1) * 2], b[nb >> 1][(nb & 1) * 2 + 1]);
        }
    };

    if (tid == 0) {
        flag_wait4(flag);                  // all 4 prep quarters published
        produce(0); produce(1);
    }

    #pragma unroll 1
    for (int k = 0; k < 8; ++k) {
        const int buf = k % 3;
        if (tid == 0 && k < 6) produce(k + 2);
        mbar_wait(mbF + buf * 8, (k / 3) & 1);   // acquire: TMA data -> ldmatrix
        compute(buf);
        if (lane == 0) mbar_arrive(mbE + buf * 8);   // warp's LDSM reads done
    }

    // ---- epilogue: acc -> smem [m][v] (stride 132) -> contiguous stores ----
    __syncthreads();                       // all compute done before smem reuse
    const float SC = 0.044194173824159216f;    // 1/sqrt(512)
    float* so = (float*)sm;
    #pragma unroll
    for (int mk = 0; mk < 4; ++mk)
        #pragma unroll
        for (int nb = 0; nb < 4; ++nb) {
            const int row = wm + mk * 16 + (lane >> 2);
            const int col = wn + nb * 8 + (lane & 3) * 2;
            float2 v0 = make_float2(acc[mk][nb][0] * SC, acc[mk][nb][1] * SC);
            float2 v1 = make_float2(acc[mk][nb][2] * SC, acc[mk][nb][3] * SC);
            *(float2*)&so[row * 132 + col]       = v0;
            *(float2*)&so[(row + 8) * 132 + col] = v1;
        }
    __syncthreads();

    constexpr int SPAN = 128 * D;              // contiguous out floats per n
    const int n0 = mb / D;

    if (D == 1) {
        const int total = 128 * 128;
        for (int t = tid; t < total; t += 256) {
            const int ni = t >> 7;
            const int vl = t & 127;
            out[(size_t)(n0 + ni) * TOT + OFF + vb + vl] = so[ni * 132 + vl];
        }
        return;
    }

    // division-free epilogue for D in {3,5,7}
    const int base = n0 * D - mb;              // in (-D, 0]
    const int n1 = (mb + 127) / D;
    const int total = (n1 - n0 + 1) * SPAN;
    constexpr int QD = 256 / D, RD = 256 % D;

    int ni = 0;                                // tid < 256 <= SPAN for D>=3
    int jj = tid;
    int vl = jj / D;                           // once, const-div
    int ii = jj - vl * D;

    for (int t = tid; t < total; t += 256) {
        const int mm = ni * D + ii + base;     // m - mb
        if (mm >= 0 && mm < 128)
            out[(size_t)(n0 + ni) * TOT + OFF + (size_t)vb * D + jj] =
                so[mm * 132 + vl];
        jj += 256; vl += QD; ii += RD;
        if (ii >= D)    { ii -= D;    vl += 1; }
        if (jj >= SPAN) { jj -= SPAN; vl -= 128; ni += 1; }
    }
}

// ---------------------------------------------------------------------------
// Merged kernel: bids [0,4096) = prep quarter-tiles (retire fast);
//                bids [4096,8192) = gemm CTAs (R11 mainloop).
// Segment splits (x4 per tile): 256 / 768 / 1280 / 1792 in both halves.
// ---------------------------------------------------------------------------
__global__ void __launch_bounds__(256, 2)
gemm_all(const float* __restrict__ x, float* __restrict__ out,
         const __grid_constant__ CUtensorMap tmX,
         const __grid_constant__ CUtensorMap tmW)
{
    extern __shared__ __align__(1024) char sm[];
    int bid = blockIdx.x;
    if (bid < 4096) {
        if      (bid < 256)  prep_body<0, 1, 0,    0>    (x, bid,        sm);
        else if (bid < 1024) prep_body<1, 3, 512,  8192> (x, bid - 256,  sm);
        else if (bid < 2304) prep_body<2, 5, 2048, 32768>(x, bid - 1024, sm);
        else                 prep_body<3, 7, 4608, 73728>(x, bid - 2304, sm);
        return;
    }
    bid -= 4096;
    if      (bid < 256)  gemm_body<0, 1, 0,    0>    (out, bid,        sm, &tmX, &tmW);
    else if (bid < 1024) gemm_body<1, 3, 512,  8192> (out, bid - 256,  sm, &tmX, &tmW);
    else if (bid < 2304) gemm_body<2, 5, 2048, 32768>(out, bid - 1024, sm, &tmX, &tmW);
    else                 gemm_body<3, 7, 4608, 73728>(out, bid - 2304, sm, &tmX, &tmW);
}

// ---------------------------------------------------------------------------
// host: tensormap construction (driver entry point; no -lcuda needed)
// ---------------------------------------------------------------------------
typedef CUresult (*EncodeFn)(CUtensorMap*, CUtensorMapDataType, cuuint32_t, void*,
                             const cuuint64_t*, const cuuint64_t*, const cuuint32_t*,
                             const cuuint32_t*, CUtensorMapInterleave, CUtensorMapSwizzle,
                             CUtensorMapL2promotion, CUtensorMapFloatOOBfill);

static EncodeFn get_encode_fn() {
    static EncodeFn fn = nullptr;
    if (!fn) {
        void* p = nullptr;
        cudaDriverEntryPointQueryResult st;
        cudaGetDriverEntryPoint("cuTensorMapEncodeTiled", &p, cudaEnableDefault, &st);
        fn = (EncodeFn)p;
    }
    return fn;
}

extern "C" void kernel_launch(void* const* d_in, const int* in_sizes, int n_in,
                              void* d_out, int out_size)
{
    const float* x  = (const float*)d_in[0];
    const float* w0 = (const float*)d_in[1];
    const float* w1 = (const float*)d_in[2];
    const float* w2 = (const float*)d_in[3];
    const float* w3 = (const float*)d_in[4];
    float* out = (float*)d_out;

    // tensormaps over the fixed __device__ scratch (stable across graph replays)
    CUtensorMap tmX{}, tmW{};
    {
        void *pX = nullptr, *pW = nullptr;
        cudaGetSymbolAddress(&pX, g_xT);
        cudaGetSymbolAddress(&pW, g_w);
        EncodeFn enc = get_encode_fn();
        cuuint64_t dimX[2] = {512, (cuuint64_t)ROWS_TOTAL};
        cuuint64_t dimW[2] = {512, 2048};
        cuuint64_t strB[1] = {1024};                     // row stride bytes
        cuuint32_t box[2]  = {64, 128};
        cuuint32_t es[2]   = {1, 1};
        enc(&tmX, CU_TENSOR_MAP_DATA_TYPE_FLOAT16, 2, pX, dimX, strB, box, es,
            CU_TENSOR_MAP_INTERLEAVE_NONE, CU_TENSOR_MAP_SWIZZLE_128B,
            CU_TENSOR_MAP_L2_PROMOTION_L2_128B, CU_TENSOR_MAP_FLOAT_OOB_FILL_NONE);
        enc(&tmW, CU_TENSOR_MAP_DATA_TYPE_FLOAT16, 2, pW, dimW, strB, box, es,
            CU_TENSOR_MAP_INTERLEAVE_NONE, CU_TENSOR_MAP_SWIZZLE_128B,
            CU_TENSOR_MAP_L2_PROMOTION_L2_128B, CU_TENSOR_MAP_FLOAT_OOB_FILL_NONE);
    }

    cudaFuncSetAttribute(gemm_all, cudaFuncAttributeMaxDynamicSharedMemorySize, SMEM_DYN);

    prep_w<<<1024, 256>>>(w0, w1, w2, w3);
    gemm_all<<<8192, 256, SMEM_DYN>>>(x, out, tmX, tmW);
}

// round 15
// speedup vs baseline: 1.0481x; 1.0481x over previous
#include <cuda_runtime.h>
#include <cuda_fp16.h>
#include <cuda.h>
#include <cstdint>

// ---------------------------------------------------------------------------
// Problem constants
// ---------------------------------------------------------------------------
constexpr int NROW = 8192;
constexpr int TOT  = 8192;
constexpr int ROWS_TOTAL = 131072;   // 8192*(1+3+5+7)

// ---------------------------------------------------------------------------
// Device scratch
// ---------------------------------------------------------------------------
__device__ __align__(128) __half g_xT[(size_t)ROWS_TOTAL * 512];   // fp16 x, K(u)-major
__device__ __align__(128) __half g_w[4 * 512 * 512];               // fp16 w, [seg][v][u]
__device__ int g_flagX[1024];                                      // per m-tile arrive counters

// ---------------------------------------------------------------------------
// PTX helpers (compute_103-safe: TMA tile / mbarrier / ldmatrix / mma.sync)
// ---------------------------------------------------------------------------
__device__ __forceinline__ uint32_t smem_u32(const void* p) {
    uint32_t a;
    asm("{ .reg .u64 t; cvta.to.shared.u64 t, %1; cvt.u32.u64 %0, t; }"
        : "=r"(a) : "l"(p));
    return a;
}
__device__ __forceinline__ uint32_t swz(uint32_t off) {        // SW128 pattern
    return off ^ ((off >> 3) & 0x70);
}
__device__ __forceinline__ void ldmx4(uint32_t* r, uint32_t addr) {
    asm volatile("ldmatrix.sync.aligned.m8n8.x4.shared.b16 {%0,%1,%2,%3}, [%4];"
        : "=r"(r[0]), "=r"(r[1]), "=r"(r[2]), "=r"(r[3]) : "r"(addr));
}
__device__ __forceinline__ void mma16816(float* c, const uint32_t* a,
                                         uint32_t b0, uint32_t b1) {
    asm volatile(
        "mma.sync.aligned.m16n8k16.row.col.f32.f16.f16.f32 "
        "{%0,%1,%2,%3}, {%4,%5,%6,%7}, {%8,%9}, {%0,%1,%2,%3};"
        : "+f"(c[0]), "+f"(c[1]), "+f"(c[2]), "+f"(c[3])
        : "r"(a[0]), "r"(a[1]), "r"(a[2]), "r"(a[3]), "r"(b0), "r"(b1));
}
__device__ __forceinline__ void mbar_init(uint32_t mbar, uint32_t cnt) {
    asm volatile("mbarrier.init.shared.b64 [%0], %1;" :: "r"(mbar), "r"(cnt) : "memory");
}
__device__ __forceinline__ void fence_proxy_async_cta() {
    asm volatile("fence.proxy.async.shared::cta;" ::: "memory");
}
__device__ __forceinline__ void mbar_expect_tx(uint32_t mbar, uint32_t bytes) {
    asm volatile("mbarrier.arrive.expect_tx.shared.b64 _, [%0], %1;"
                 :: "r"(mbar), "r"(bytes) : "memory");
}
__device__ __forceinline__ void mbar_arrive(uint32_t mbar) {
    asm volatile("mbarrier.arrive.shared.b64 _, [%0];" :: "r"(mbar) : "memory");
}
__device__ __forceinline__ void mbar_wait(uint32_t mbar, uint32_t parity) {
    asm volatile(
        "{\n\t.reg .pred P;\n"
        "W%=:\n\t"
        "mbarrier.try_wait.parity.acquire.cta.shared::cta.b64 P, [%0], %1, 0x989680;\n\t"
        "@!P bra W%=;\n\t}"
        :: "r"(mbar), "r"(parity) : "memory");
}
__device__ __forceinline__ void tma2d(uint32_t smem, const void* map,
                                      int c0, int c1, uint32_t mbar) {
    asm volatile(
        "cp.async.bulk.tensor.2d.shared::cta.global.tile.mbarrier::complete_tx::bytes "
        "[%0], [%1, {%2, %3}], [%4];"
        :: "r"(smem), "l"(map), "r"(c0), "r"(c1), "r"(mbar) : "memory");
}
__device__ __forceinline__ void flag_wait4(const int* p) {
    uint32_t v;
    do {
        asm volatile("ld.acquire.gpu.global.u32 %0, [%1];" : "=r"(v) : "l"(p) : "memory");
        if (v < 4) __nanosleep(128);
    } while (v < 4);
}

// ---------------------------------------------------------------------------
// prep_w: w -> fp16 transposed [v][u]; block 0 also resets the X-ready flags.
// ---------------------------------------------------------------------------
__global__ void __launch_bounds__(256)
prep_w(const float* __restrict__ w0, const float* __restrict__ w1,
       const float* __restrict__ w2, const float* __restrict__ w3)
{
    __shared__ float t[32][33];
    const int tid = threadIdx.x;
    if (blockIdx.x == 0)
        for (int i = tid; i < 1024; i += 256) g_flagX[i] = 0;

    const int bz = blockIdx.x >> 8, bx = blockIdx.x & 15, by = (blockIdx.x >> 4) & 15;
    const float* w = (bz == 0) ? w0 : (bz == 1) ? w1 : (bz == 2) ? w2 : w3;
    const int v0 = bx * 32, u0 = by * 32;
    const int tx = tid & 31, ty = tid >> 5;

    for (int uu = ty; uu < 32; uu += 8)
        t[uu][tx] = w[(size_t)(u0 + uu) * 512 + v0 + tx];
    __syncthreads();

    const size_t segb = (size_t)bz * 262144;
    for (int vv = ty; vv < 32; vv += 8)
        g_w[segb + (size_t)(v0 + vv) * 512 + u0 + tx] = __float2half_rn(t[tx][vv]);
}

// ---------------------------------------------------------------------------
// Prep body (dedicated CTAs): convert one QUARTER tile (32 m-rows) of x into
// g_xT, publish via atomic counter, retire.  (Validated in R13/R14.)
// ---------------------------------------------------------------------------
constexpr int STAGE    = 32768;              // X 16K + W 16K
constexpr int MBAR_OFF = 3 * STAGE;          // 98304
constexpr int SMEM_DYN = MBAR_OFF + 48;      // + 3 full + 3 empty mbars

template<int SEG, int D, int OFF, int ROWBASE>
__device__ __forceinline__ void prep_body(const float* __restrict__ x, int lb4, char* sm)
{
    const int tid = threadIdx.x;
    const int mb  = (lb4 >> 2) * 128;
    const int q   = lb4 & 3;
    const int m0  = mb + q * 32;                   // [m0, m0+32)
    const int nA  = m0 / D;
    const int nB  = (m0 + 31) / D;
    const int cnt = nB - nA + 1;                   // <= 32 n-rows (D=1)
    float* sx = (float*)sm;                        // up to 86 KB used
    constexpr int SLAB = 512 * D;                  // floats per n

    const int nf4 = cnt * (SLAB / 4);
    for (int idx = tid; idx < nf4; idx += 256) {
        const int nl = idx / (SLAB / 4);
        const int r4 = idx - nl * (SLAB / 4);
        ((float4*)sx)[idx] =
            *(const float4*)(x + (size_t)(nA + nl) * TOT + OFF + r4 * 4);
    }
    __syncthreads();

    for (int e2 = tid; e2 < 32 * 256; e2 += 256) { // 32 rows x 256 half2
        const int mr = e2 >> 8;
        const int u2 = (e2 & 255) * 2;
        const int m  = m0 + mr;
        const int n  = m / D;                      // constexpr D: mul-shift
        const int i  = m - n * D;
        const float* s = sx + (n - nA) * SLAB;
        __half2 p;
        p.x = __float2half_rn(s[u2 * D + i]);
        p.y = __float2half_rn(s[(u2 + 1) * D + i]);
        *(__half2*)&g_xT[((size_t)ROWBASE + m) * 512 + u2] = p;
    }
    __threadfence();                               // publish (gpu scope)
    __syncthreads();
    if (tid == 0) atomicAdd(&g_flagX[ROWBASE / 128 + (lb4 >> 2)], 1);
}

// ---------------------------------------------------------------------------
// Main GEMM body (R11-validated): TMA 3-stage ring, no syncthreads in loop.
// tid 0 waits for its tile's 4 prep quarters before the first TMA.
// ---------------------------------------------------------------------------
template<int SEG, int D, int OFF, int ROWBASE>
__device__ __forceinline__ void gemm_body(float* __restrict__ out, int lb, char* sm,
                                          const CUtensorMap* tmX, const CUtensorMap* tmW)
{
    const int tid  = threadIdx.x;
    const int lane = tid & 31;
    const int wid  = tid >> 5;
    const int vb   = (lb & 3) * 128;       // v-tile base (fast -> L2 X reuse)
    const int mb   = (lb >> 2) * 128;      // m-tile base
    const int wm   = (wid & 1) * 64;       // warp M offset (2x4 warp grid)
    const int wn   = (wid >> 1) * 32;      // warp N offset
    const uint32_t smb = smem_u32(sm);
    const uint32_t mbF = smb + MBAR_OFF;       // full[3]
    const uint32_t mbE = smb + MBAR_OFF + 24;  // empty[3]
    const int* flag = &g_flagX[ROWBASE / 128 + (lb >> 2)];

    if (tid == 0) {
        #pragma unroll
        for (int b = 0; b < 3; ++b) {
            mbar_init(mbF + b * 8, 1);     // completed by expect_tx + TMA tx
            mbar_init(mbE + b * 8, 8);     // one arrive per warp
        }
        fence_proxy_async_cta();           // init visible to async (TMA) proxy
    }
    __syncthreads();

    // producer: chunk j -> buffer j%3.  empty parity: ((j/3)&1)^1 (first pass free)
    auto produce = [&](int j) {
        const int buf = j % 3;
        const uint32_t fm = mbF + buf * 8;
        mbar_wait(mbE + buf * 8, ((j / 3) & 1) ^ 1);
        mbar_expect_tx(fm, 2 * 16384);
        tma2d(smb + buf * STAGE,         tmX, j * 64, ROWBASE + mb,  fm);
        tma2d(smb + buf * STAGE + 16384, tmW, j * 64, SEG * 512 + vb, fm);
    };

    float acc[4][4][4] = {};

    // ldmatrix lane addressing (swizzle computed per-ks: swz does NOT
    // distribute over +ks*32 when the XOR pattern occupies bits 5-6!)
    const int a_m  = (lane & 7) + ((lane >> 3) & 1) * 8;
    const int a_kb = ((lane >> 4) & 1) * 16;
    const int b_n  = (lane & 7) + ((lane >> 4) & 1) * 8;
    const int b_kb = ((lane >> 3) & 1) * 16;
    const uint32_t aBase = (uint32_t)((wm + a_m) * 128 + a_kb);
    const uint32_t bBase = (uint32_t)((wn + b_n) * 128 + b_kb);

    auto compute = [&](int buf) {
        const uint32_t baseX = smb + buf * STAGE;
        const uint32_t baseW = baseX + 16384;
        #pragma unroll
        for (int ks = 0; ks < 4; ++ks) {
            uint32_t a[4][4], b[2][4];
            const uint32_t aA = baseX + swz(aBase + ks * 32);
            const uint32_t bA = baseW + swz(bBase + ks * 32);
            #pragma unroll
            for (int mk = 0; mk < 4; ++mk) ldmx4(a[mk], aA + mk * 2048);
            #pragma unroll
            for (int nh = 0; nh < 2; ++nh) ldmx4(b[nh], bA + nh * 2048);
            #pragma unroll
            for (int mk = 0; mk < 4; ++mk)
                #pragma unroll
                for (int nb = 0; nb < 4; ++nb)
                    mma16816(acc[mk][nb], a[mk],
                             b[nb >> 1][(nb & 1) * 2], b[nb >> 1][(nb & 1) * 2 + 1]);
        }
    };

    if (tid == 0) {
        flag_wait4(flag);                  // all 4 prep quarters published
        produce(0); produce(1);
    }

    #pragma unroll 1
    for (int k = 0; k < 8; ++k) {
        const int buf = k % 3;
        if (tid == 0 && k < 6) produce(k + 2);
        mbar_wait(mbF + buf * 8, (k / 3) & 1);   // acquire: TMA data -> ldmatrix
        compute(buf);
        if (lane == 0) mbar_arrive(mbE + buf * 8);   // warp's LDSM reads done
    }

    // ---- epilogue: acc -> smem [m][v] (stride 132) -> contiguous stores ----
    __syncthreads();                       // all compute done before smem reuse
    const float SC = 0.044194173824159216f;    // 1/sqrt(512)
    float* so = (float*)sm;
    #pragma unroll
    for (int mk = 0; mk < 4; ++mk)
        #pragma unroll
        for (int nb = 0; nb < 4; ++nb) {
            const int row = wm + mk * 16 + (lane >> 2);
            const int col = wn + nb * 8 + (lane & 3) * 2;
            float2 v0 = make_float2(acc[mk][nb][0] * SC, acc[mk][nb][1] * SC);
            float2 v1 = make_float2(acc[mk][nb][2] * SC, acc[mk][nb][3] * SC);
            *(float2*)&so[row * 132 + col]       = v0;
            *(float2*)&so[(row + 8) * 132 + col] = v1;
        }
    __syncthreads();

    constexpr int SPAN = 128 * D;              // contiguous out floats per n
    const int n0 = mb / D;

    if (D == 1) {
        const int total = 128 * 128;
        for (int t = tid; t < total; t += 256) {
            const int ni = t >> 7;
            const int vl = t & 127;
            out[(size_t)(n0 + ni) * TOT + OFF + vb + vl] = so[ni * 132 + vl];
        }
        return;
    }

    // division-free epilogue for D in {3,5,7}
    const int base = n0 * D - mb;              // in (-D, 0]
    const int n1 = (mb + 127) / D;
    const int total = (n1 - n0 + 1) * SPAN;
    constexpr int QD = 256 / D, RD = 256 % D;

    int ni = 0;                                // tid < 256 <= SPAN for D>=3
    int jj = tid;
    int vl = jj / D;                           // once, const-div
    int ii = jj - vl * D;

    for (int t = tid; t < total; t += 256) {
        const int mm = ni * D + ii + base;     // m - mb
        if (mm >= 0 && mm < 128)
            out[(size_t)(n0 + ni) * TOT + OFF + (size_t)vb * D + jj] =
                so[mm * 132 + vl];
        jj += 256; vl += QD; ii += RD;
        if (ii >= D)    { ii -= D;    vl += 1; }
        if (jj >= SPAN) { jj -= SPAN; vl -= 128; ni += 1; }
    }
}

// ---------------------------------------------------------------------------
// Merged kernel with INTERLEAVED prep/gemm bids (prep leads by DELTA tiles):
//   bids [0, 256):        prep quarters of tiles 0..63 (prologue)
//   bids [256, 7936):     960 blocks of 8 = [4 prep quarters of tile blk+64 |
//                                            4 gemm CTAs of tile blk]
//   bids [7936, 8192):    gemm CTAs of tiles 960..1023 (tail)
// Tile t -> segment: t<64 seg0, t<256 seg1, t<576 seg2, else seg3.
// ---------------------------------------------------------------------------
__global__ void __launch_bounds__(256, 2)
gemm_all(const float* __restrict__ x, float* __restrict__ out,
         const __grid_constant__ CUtensorMap tmX,
         const __grid_constant__ CUtensorMap tmW)
{
    extern __shared__ __align__(1024) char sm[];
    const int bid = blockIdx.x;
    int tile, sub;
    bool isPrep;
    if (bid < 256) {
        isPrep = true;  tile = bid >> 2;          sub = bid & 3;
    } else if (bid < 7936) {
        const int r = bid - 256, blk = r >> 3, w = r & 7;
        if (w < 4) { isPrep = true;  tile = blk + 64; sub = w;     }
        else       { isPrep = false; tile = blk;      sub = w - 4; }
    } else {
        const int r = bid - 7936;
        isPrep = false; tile = 960 + (r >> 2);    sub = r & 3;
    }

    if (isPrep) {
        if      (tile < 64)  prep_body<0, 1, 0,    0>    (x, tile * 4 + sub,         sm);
        else if (tile < 256) prep_body<1, 3, 512,  8192> (x, (tile - 64) * 4 + sub,  sm);
        else if (tile < 576) prep_body<2, 5, 2048, 32768>(x, (tile - 256) * 4 + sub, sm);
        else                 prep_body<3, 7, 4608, 73728>(x, (tile - 576) * 4 + sub, sm);
    } else {
        if      (tile < 64)  gemm_body<0, 1, 0,    0>    (out, tile * 4 + sub,         sm, &tmX, &tmW);
        else if (tile < 256) gemm_body<1, 3, 512,  8192> (out, (tile - 64) * 4 + sub,  sm, &tmX, &tmW);
        else if (tile < 576) gemm_body<2, 5, 2048, 32768>(out, (tile - 256) * 4 + sub, sm, &tmX, &tmW);
        else                 gemm_body<3, 7, 4608, 73728>(out, (tile - 576) * 4 + sub, sm, &tmX, &tmW);
    }
}

// ---------------------------------------------------------------------------
// host: tensormap construction (driver entry point; no -lcuda needed)
// ---------------------------------------------------------------------------
typedef CUresult (*EncodeFn)(CUtensorMap*, CUtensorMapDataType, cuuint32_t, void*,
                             const cuuint64_t*, const cuuint64_t*, const cuuint32_t*,
                             const cuuint32_t*, CUtensorMapInterleave, CUtensorMapSwizzle,
                             CUtensorMapL2promotion, CUtensorMapFloatOOBfill);

static EncodeFn get_encode_fn() {
    static EncodeFn fn = nullptr;
    if (!fn) {
        void* p = nullptr;
        cudaDriverEntryPointQueryResult st;
        cudaGetDriverEntryPoint("cuTensorMapEncodeTiled", &p, cudaEnableDefault, &st);
        fn = (EncodeFn)p;
    }
    return fn;
}

extern "C" void kernel_launch(void* const* d_in, const int* in_sizes, int n_in,
                              void* d_out, int out_size)
{
    const float* x  = (const float*)d_in[0];
    const float* w0 = (const float*)d_in[1];
    const float* w1 = (const float*)d_in[2];
    const float* w2 = (const float*)d_in[3];
    const float* w3 = (const float*)d_in[4];
    float* out = (float*)d_out;

    // tensormaps over the fixed __device__ scratch (stable across graph replays)
    CUtensorMap tmX{}, tmW{};
    {
        void *pX = nullptr, *pW = nullptr;
        cudaGetSymbolAddress(&pX, g_xT);
        cudaGetSymbolAddress(&pW, g_w);
        EncodeFn enc = get_encode_fn();
        cuuint64_t dimX[2] = {512, (cuuint64_t)ROWS_TOTAL};
        cuuint64_t dimW[2] = {512, 2048};
        cuuint64_t strB[1] = {1024};                     // row stride bytes
        cuuint32_t box[2]  = {64, 128};
        cuuint32_t es[2]   = {1, 1};
        enc(&tmX, CU_TENSOR_MAP_DATA_TYPE_FLOAT16, 2, pX, dimX, strB, box, es,
            CU_TENSOR_MAP_INTERLEAVE_NONE, CU_TENSOR_MAP_SWIZZLE_128B,
            CU_TENSOR_MAP_L2_PROMOTION_L2_128B, CU_TENSOR_MAP_FLOAT_OOB_FILL_NONE);
        enc(&tmW, CU_TENSOR_MAP_DATA_TYPE_FLOAT16, 2, pW, dimW, strB, box, es,
            CU_TENSOR_MAP_INTERLEAVE_NONE, CU_TENSOR_MAP_SWIZZLE_128B,
            CU_TENSOR_MAP_L2_PROMOTION_L2_128B, CU_TENSOR_MAP_FLOAT_OOB_FILL_NONE);
    }

    cudaFuncSetAttribute(gemm_all, cudaFuncAttributeMaxDynamicSharedMemorySize, SMEM_DYN);

    prep_w<<<1024, 256>>>(w0, w1, w2, w3);
    gemm_all<<<8192, 256, SMEM_DYN>>>(x, out, tmX, tmW);
}

// round 16
// speedup vs baseline: 1.1663x; 1.1128x over previous
#include <cuda_runtime.h>
#include <cuda_fp16.h>
#include <cuda.h>
#include <cstdint>

// ---------------------------------------------------------------------------
// Problem constants
// ---------------------------------------------------------------------------
constexpr int NROW = 8192;
constexpr int TOT  = 8192;
constexpr int ROWS_TOTAL = 131072;   // 8192*(1+3+5+7)

// ---------------------------------------------------------------------------
// Device scratch
// ---------------------------------------------------------------------------
__device__ __align__(128) __half g_xT[(size_t)ROWS_TOTAL * 512];   // fp16 x, K(u)-major
__device__ __align__(128) __half g_w[4 * 512 * 512];               // fp16 w, [seg][v][u]

// ---------------------------------------------------------------------------
// PTX helpers (compute_103-safe: TMA tile / mbarrier / ldmatrix / mma.sync)
// ---------------------------------------------------------------------------
__device__ __forceinline__ uint32_t smem_u32(const void* p) {
    uint32_t a;
    asm("{ .reg .u64 t; cvta.to.shared.u64 t, %1; cvt.u32.u64 %0, t; }"
        : "=r"(a) : "l"(p));
    return a;
}
__device__ __forceinline__ uint32_t swz(uint32_t off) {        // SW128 pattern
    return off ^ ((off >> 3) & 0x70);
}
__device__ __forceinline__ void ldmx4(uint32_t* r, uint32_t addr) {
    asm volatile("ldmatrix.sync.aligned.m8n8.x4.shared.b16 {%0,%1,%2,%3}, [%4];"
        : "=r"(r[0]), "=r"(r[1]), "=r"(r[2]), "=r"(r[3]) : "r"(addr));
}
__device__ __forceinline__ void mma16816(float* c, const uint32_t* a,
                                         uint32_t b0, uint32_t b1) {
    asm volatile(
        "mma.sync.aligned.m16n8k16.row.col.f32.f16.f16.f32 "
        "{%0,%1,%2,%3}, {%4,%5,%6,%7}, {%8,%9}, {%0,%1,%2,%3};"
        : "+f"(c[0]), "+f"(c[1]), "+f"(c[2]), "+f"(c[3])
        : "r"(a[0]), "r"(a[1]), "r"(a[2]), "r"(a[3]), "r"(b0), "r"(b1));
}
__device__ __forceinline__ void mbar_init(uint32_t mbar, uint32_t cnt) {
    asm volatile("mbarrier.init.shared.b64 [%0], %1;" :: "r"(mbar), "r"(cnt) : "memory");
}
__device__ __forceinline__ void fence_proxy_async_cta() {
    asm volatile("fence.proxy.async.shared::cta;" ::: "memory");
}
__device__ __forceinline__ void mbar_expect_tx(uint32_t mbar, uint32_t bytes) {
    asm volatile("mbarrier.arrive.expect_tx.shared.b64 _, [%0], %1;"
                 :: "r"(mbar), "r"(bytes) : "memory");
}
__device__ __forceinline__ void mbar_arrive(uint32_t mbar) {
    asm volatile("mbarrier.arrive.shared.b64 _, [%0];" :: "r"(mbar) : "memory");
}
__device__ __forceinline__ void mbar_wait(uint32_t mbar, uint32_t parity) {
    asm volatile(
        "{\n\t.reg .pred P;\n"
        "W%=:\n\t"
        "mbarrier.try_wait.parity.acquire.cta.shared::cta.b64 P, [%0], %1, 0x989680;\n\t"
        "@!P bra W%=;\n\t}"
        :: "r"(mbar), "r"(parity) : "memory");
}
__device__ __forceinline__ void tma2d(uint32_t smem, const void* map,
                                      int c0, int c1, uint32_t mbar) {
    asm volatile(
        "cp.async.bulk.tensor.2d.shared::cta.global.tile.mbarrier::complete_tx::bytes "
        "[%0], [%1, {%2, %3}], [%4];"
        :: "r"(smem), "l"(map), "r"(c0), "r"(c1), "r"(mbar) : "memory");
}

// ---------------------------------------------------------------------------
// Merged prep: blocks [0,8192) transpose/convert x; blocks [8192,9216) do w.
// ---------------------------------------------------------------------------
__global__ void __launch_bounds__(256)
prep_all(const float* __restrict__ x,
         const float* __restrict__ w0, const float* __restrict__ w1,
         const float* __restrict__ w2, const float* __restrict__ w3)
{
    __shared__ float sx[3584];
    const int tid = threadIdx.x;

    if (blockIdx.x >= 8192) {
        // ---- w prep: 1024 blocks, 32x32 transpose tiles ----
        const int wb = blockIdx.x - 8192;
        const int bz = wb >> 8, bx = wb & 15, by = (wb >> 4) & 15;
        const float* w = (bz == 0) ? w0 : (bz == 1) ? w1 : (bz == 2) ? w2 : w3;
        const int v0 = bx * 32, u0 = by * 32;
        const int tx = tid & 31, ty = tid >> 5;
        float (*t)[33] = (float(*)[33])sx;

        for (int uu = ty; uu < 32; uu += 8)
            t[uu][tx] = w[(size_t)(u0 + uu) * 512 + v0 + tx];
        __syncthreads();

        const size_t segb = (size_t)bz * 262144;
        for (int vv = ty; vv < 32; vv += 8)
            g_w[segb + (size_t)(v0 + vv) * 512 + u0 + tx] = __float2half_rn(t[tx][vv]);
        return;
    }

    // ---- x prep: per-row transpose [u][i] -> [(n,i)][u], fp16 ----
    const int n = blockIdx.x;

    // D=1 fast path: no transpose (i==0), direct float2 -> half2 copy.
    {
        const float2* src = (const float2*)(x + (size_t)n * TOT);
        __half2* dst = (__half2*)&g_xT[(size_t)n * 512];
        if (tid < 256) {
            const float2 v = src[tid];
            __half2 p; p.x = __float2half_rn(v.x); p.y = __float2half_rn(v.y);
            dst[tid] = p;
        }
    }

    #pragma unroll
    for (int s = 1; s < 4; ++s) {
        const int d   = (s == 1) ? 3 : (s == 2) ? 5 : 7;
        const int off = (s == 1) ? 512 : (s == 2) ? 2048 : 4608;
        const int rb  = (s == 1) ? 8192 : (s == 2) ? 32768 : 73728;
        const int nf  = 512 * d;

        const float4* src = (const float4*)(x + (size_t)n * TOT + off);
        for (int idx = tid; idx < nf / 4; idx += 256)
            ((float4*)sx)[idx] = src[idx];
        __syncthreads();

        for (int e2 = tid; e2 < nf / 2; e2 += 256) {
            const int e = 2 * e2;
            const int u = e & 511;          // e = i*512 + u
            const int i = e >> 9;
            __half2 p;
            p.x = __float2half_rn(sx[u * d + i]);
            p.y = __float2half_rn(sx[(u + 1) * d + i]);
            *(__half2*)&g_xT[((size_t)rb + (size_t)n * d + i) * 512 + u] = p;
        }
        __syncthreads();
    }
}

// ---------------------------------------------------------------------------
// Main GEMM body (mma.sync fp16, TMA 3-stage pipeline, no syncthreads in loop)
//   C[m=(n,i)][v] = sum_u X[m][u] * W[v][u];  scaled in fp32 epilogue.
// CTA tile 128x128, warp tile 64x32, BK=64, 2 CTAs/SM (16 warps/SM).
// ---------------------------------------------------------------------------
constexpr int STAGE    = 32768;              // X 16K + W 16K
constexpr int MBAR_OFF = 3 * STAGE;          // 98304
constexpr int SMEM_DYN = MBAR_OFF + 48;      // + 3 full + 3 empty mbars

template<int SEG, int D, int OFF, int ROWBASE>
__device__ __forceinline__ void gemm_body(float* __restrict__ out, int lb, char* sm,
                                          const CUtensorMap* tmX, const CUtensorMap* tmW)
{
    const int tid  = threadIdx.x;
    const int lane = tid & 31;
    const int wid  = tid >> 5;
    const int vb   = (lb & 3) * 128;       // v-tile base (fast -> L2 X reuse)
    const int mb   = (lb >> 2) * 128;      // m-tile base
    const int wm   = (wid & 1) * 64;       // warp M offset (2x4 warp grid)
    const int wn   = (wid >> 1) * 32;      // warp N offset
    const uint32_t smb = smem_u32(sm);
    const uint32_t mbF = smb + MBAR_OFF;       // full[3]
    const uint32_t mbE = smb + MBAR_OFF + 24;  // empty[3]

    if (tid == 0) {
        #pragma unroll
        for (int b = 0; b < 3; ++b) {
            mbar_init(mbF + b * 8, 1);     // completed by expect_tx + TMA tx
            mbar_init(mbE + b * 8, 8);     // one arrive per warp
        }
        fence_proxy_async_cta();           // init visible to async (TMA) proxy
    }
    __syncthreads();

    // producer: chunk j -> buffer j%3.  empty parity: ((j/3)&1)^1 (first pass free)
    auto produce = [&](int j, int buf, uint32_t epar) {
        const uint32_t fm = mbF + buf * 8;
        mbar_wait(mbE + buf * 8, epar);
        mbar_expect_tx(fm, 2 * 16384);
        tma2d(smb + buf * STAGE,         tmX, j * 64, ROWBASE + mb,  fm);
        tma2d(smb + buf * STAGE + 16384, tmW, j * 64, SEG * 512 + vb, fm);
    };

    float acc[4][4][4] = {};

    // ldmatrix lane addressing.  Bits 5-6 of aBase/bBase (pre-swizzle) are
    // zero (row*128 >= bit7, kb in {0,16} = bit4) and the SW128 XOR pattern
    // depends only on bits 7-9, so: swz(base + ks*32) == swz(base) ^ (ks*32).
    const int a_m  = (lane & 7) + ((lane >> 3) & 1) * 8;
    const int a_kb = ((lane >> 4) & 1) * 16;
    const int b_n  = (lane & 7) + ((lane >> 4) & 1) * 8;
    const int b_kb = ((lane >> 3) & 1) * 16;
    const uint32_t aSwz = swz((uint32_t)((wm + a_m) * 128 + a_kb));
    const uint32_t bSwz = swz((uint32_t)((wn + b_n) * 128 + b_kb));

    auto compute = [&](int buf) {
        const uint32_t baseX = smb + buf * STAGE;
        const uint32_t baseW = baseX + 16384;
        #pragma unroll
        for (int ks = 0; ks < 4; ++ks) {
            uint32_t a[4][4], b[2][4];
            const uint32_t aA = baseX + (aSwz ^ (uint32_t)(ks * 32));
            const uint32_t bA = baseW + (bSwz ^ (uint32_t)(ks * 32));
            #pragma unroll
            for (int mk = 0; mk < 4; ++mk) ldmx4(a[mk], aA + mk * 2048);
            #pragma unroll
            for (int nh = 0; nh < 2; ++nh) ldmx4(b[nh], bA + nh * 2048);
            #pragma unroll
            for (int mk = 0; mk < 4; ++mk)
                #pragma unroll
                for (int nb = 0; nb < 4; ++nb)
                    mma16816(acc[mk][nb], a[mk],
                             b[nb >> 1][(nb & 1) * 2], b[nb >> 1][(nb & 1) * 2 + 1]);
        }
    };

    if (tid == 0) { produce(0, 0, 1); produce(1, 1, 1); }

    // incremental ring counters (no div/mod in the loop)
    int cbuf = 0, cpar = 0;                 // consumer: buffer, full-parity
    int pbuf = 2, ppar = 1;                 // producer: buffer, empty-parity
    #pragma unroll 1
    for (int k = 0; k < 8; ++k) {
        if (tid == 0 && k < 6) {
            produce(k + 2, pbuf, ppar);
            if (++pbuf == 3) { pbuf = 0; ppar ^= 1; }
        }
        mbar_wait(mbF + cbuf * 8, cpar);    // acquire: TMA data -> ldmatrix
        compute(cbuf);
        if (lane == 0) mbar_arrive(mbE + cbuf * 8);   // warp's LDSM reads done
        if (++cbuf == 3) { cbuf = 0; cpar ^= 1; }
    }

    // ---- epilogue: acc -> smem [m][v] (stride 132) -> contiguous stores ----
    __syncthreads();                       // all compute done before smem reuse
    const float SC = 0.044194173824159216f;    // 1/sqrt(512)
    float* so = (float*)sm;
    #pragma unroll
    for (int mk = 0; mk < 4; ++mk)
        #pragma unroll
        for (int nb = 0; nb < 4; ++nb) {
            const int row = wm + mk * 16 + (lane >> 2);
            const int col = wn + nb * 8 + (lane & 3) * 2;
            float2 v0 = make_float2(acc[mk][nb][0] * SC, acc[mk][nb][1] * SC);
            float2 v1 = make_float2(acc[mk][nb][2] * SC, acc[mk][nb][3] * SC);
            *(float2*)&so[row * 132 + col]       = v0;
            *(float2*)&so[(row + 8) * 132 + col] = v1;
        }
    __syncthreads();

    constexpr int SPAN = 128 * D;              // contiguous out floats per n
    const int n0 = mb / D;

    if (D == 1) {
        const int total = 128 * 128;
        for (int t = tid; t < total; t += 256) {
            const int ni = t >> 7;
            const int vl = t & 127;
            out[(size_t)(n0 + ni) * TOT + OFF + vb + vl] = so[ni * 132 + vl];
        }
        return;
    }

    // division-free epilogue for D in {3,5,7}
    const int base = n0 * D - mb;              // in (-D, 0]
    const int n1 = (mb + 127) / D;
    const int total = (n1 - n0 + 1) * SPAN;
    constexpr int QD = 256 / D, RD = 256 % D;

    int ni = 0;                                // tid < 256 <= SPAN for D>=3
    int jj = tid;
    int vl = jj / D;                           // once, const-div
    int ii = jj - vl * D;

    for (int t = tid; t < total; t += 256) {
        const int mm = ni * D + ii + base;     // m - mb
        if (mm >= 0 && mm < 128)
            out[(size_t)(n0 + ni) * TOT + OFF + (size_t)vb * D + jj] =
                so[mm * 132 + vl];
        jj += 256; vl += QD; ii += RD;
        if (ii >= D)    { ii -= D;    vl += 1; }
        if (jj >= SPAN) { jj -= SPAN; vl -= 128; ni += 1; }
    }
}

// Merged kernel: all 4 segments in one launch (single tail wave).
// seg CTA counts: 256 / 768 / 1280 / 1792  (total 4096)
__global__ void __launch_bounds__(256, 2)
gemm_all(float* __restrict__ out,
         const __grid_constant__ CUtensorMap tmX,
         const __grid_constant__ CUtensorMap tmW)
{
    extern __shared__ __align__(1024) char sm[];
    const int bid = blockIdx.x;
    if      (bid < 256)  gemm_body<0, 1, 0,    0>    (out, bid,        sm, &tmX, &tmW);
    else if (bid < 1024) gemm_body<1, 3, 512,  8192> (out, bid - 256,  sm, &tmX, &tmW);
    else if (bid < 2304) gemm_body<2, 5, 2048, 32768>(out, bid - 1024, sm, &tmX, &tmW);
    else                 gemm_body<3, 7, 4608, 73728>(out, bid - 2304, sm, &tmX, &tmW);
}

// ---------------------------------------------------------------------------
// host: tensormap construction (driver entry point; no -lcuda needed)
// ---------------------------------------------------------------------------
typedef CUresult (*EncodeFn)(CUtensorMap*, CUtensorMapDataType, cuuint32_t, void*,
                             const cuuint64_t*, const cuuint64_t*, const cuuint32_t*,
                             const cuuint32_t*, CUtensorMapInterleave, CUtensorMapSwizzle,
                             CUtensorMapL2promotion, CUtensorMapFloatOOBfill);

static EncodeFn get_encode_fn() {
    static EncodeFn fn = nullptr;
    if (!fn) {
        void* p = nullptr;
        cudaDriverEntryPointQueryResult st;
        cudaGetDriverEntryPoint("cuTensorMapEncodeTiled", &p, cudaEnableDefault, &st);
        fn = (EncodeFn)p;
    }
    return fn;
}

extern "C" void kernel_launch(void* const* d_in, const int* in_sizes, int n_in,
                              void* d_out, int out_size)
{
    const float* x  = (const float*)d_in[0];
    const float* w0 = (const float*)d_in[1];
    const float* w1 = (const float*)d_in[2];
    const float* w2 = (const float*)d_in[3];
    const float* w3 = (const float*)d_in[4];
    float* out = (float*)d_out;

    // tensormaps over the fixed __device__ scratch (stable across graph replays)
    CUtensorMap tmX{}, tmW{};
    {
        void *pX = nullptr, *pW = nullptr;
        cudaGetSymbolAddress(&pX, g_xT);
        cudaGetSymbolAddress(&pW, g_w);
        EncodeFn enc = get_encode_fn();
        cuuint64_t dimX[2] = {512, (cuuint64_t)ROWS_TOTAL};
        cuuint64_t dimW[2] = {512, 2048};
        cuuint64_t strB[1] = {1024};                     // row stride bytes
        cuuint32_t box[2]  = {64, 128};
        cuuint32_t es[2]   = {1, 1};
        enc(&tmX, CU_TENSOR_MAP_DATA_TYPE_FLOAT16, 2, pX, dimX, strB, box, es,
            CU_TENSOR_MAP_INTERLEAVE_NONE, CU_TENSOR_MAP_SWIZZLE_128B,
            CU_TENSOR_MAP_L2_PROMOTION_L2_128B, CU_TENSOR_MAP_FLOAT_OOB_FILL_NONE);
        enc(&tmW, CU_TENSOR_MAP_DATA_TYPE_FLOAT16, 2, pW, dimW, strB, box, es,
            CU_TENSOR_MAP_INTERLEAVE_NONE, CU_TENSOR_MAP_SWIZZLE_128B,
            CU_TENSOR_MAP_L2_PROMOTION_L2_128B, CU_TENSOR_MAP_FLOAT_OOB_FILL_NONE);
    }

    cudaFuncSetAttribute(gemm_all, cudaFuncAttributeMaxDynamicSharedMemorySize, SMEM_DYN);

    prep_all<<<9216, 256>>>(x, w0, w1, w2, w3);
    gemm_all<<<4096, 256, SMEM_DYN>>>(out, tmX, tmW);
}

// round 17
// speedup vs baseline: 1.2083x; 1.0361x over previous
#include <cuda_runtime.h>
#include <cuda_fp16.h>
#include <cuda.h>
#include <cstdint>

// ---------------------------------------------------------------------------
// Problem constants
// ---------------------------------------------------------------------------
constexpr int NROW = 8192;
constexpr int TOT  = 8192;
constexpr int ROWS_TOTAL = 131072;   // 8192*(1+3+5+7)

// ---------------------------------------------------------------------------
// Device scratch
// ---------------------------------------------------------------------------
__device__ __align__(128) __half g_xT[(size_t)ROWS_TOTAL * 512];   // fp16 x, K(u)-major
__device__ __align__(128) __half g_w[4 * 512 * 512];               // fp16 w*SC, [seg][v][u]

// ---------------------------------------------------------------------------
// PTX helpers (compute_103-safe: TMA tile / cp.async / mbarrier / ldmatrix / mma.sync)
// ---------------------------------------------------------------------------
__device__ __forceinline__ uint32_t smem_u32(const void* p) {
    uint32_t a;
    asm("{ .reg .u64 t; cvta.to.shared.u64 t, %1; cvt.u32.u64 %0, t; }"
        : "=r"(a) : "l"(p));
    return a;
}
__device__ __forceinline__ uint32_t swz(uint32_t off) {        // SW128 pattern
    return off ^ ((off >> 3) & 0x70);
}
__device__ __forceinline__ void cpa16(uint32_t s, const void* g) {
    asm volatile("cp.async.cg.shared.global [%0], [%1], 16;" :: "r"(s), "l"(g));
}
template<int N> __device__ __forceinline__ void cpwait() {
    asm volatile("cp.async.wait_group %0;" :: "n"(N) : "memory");
}
__device__ __forceinline__ void cpcommit() {
    asm volatile("cp.async.commit_group;" ::: "memory");
}
__device__ __forceinline__ void ldmx4(uint32_t* r, uint32_t addr) {
    asm volatile("ldmatrix.sync.aligned.m8n8.x4.shared.b16 {%0,%1,%2,%3}, [%4];"
        : "=r"(r[0]), "=r"(r[1]), "=r"(r[2]), "=r"(r[3]) : "r"(addr));
}
__device__ __forceinline__ void mma16816(float* c, const uint32_t* a,
                                         uint32_t b0, uint32_t b1) {
    asm volatile(
        "mma.sync.aligned.m16n8k16.row.col.f32.f16.f16.f32 "
        "{%0,%1,%2,%3}, {%4,%5,%6,%7}, {%8,%9}, {%0,%1,%2,%3};"
        : "+f"(c[0]), "+f"(c[1]), "+f"(c[2]), "+f"(c[3])
        : "r"(a[0]), "r"(a[1]), "r"(a[2]), "r"(a[3]), "r"(b0), "r"(b1));
}
__device__ __forceinline__ void mbar_init(uint32_t mbar, uint32_t cnt) {
    asm volatile("mbarrier.init.shared.b64 [%0], %1;" :: "r"(mbar), "r"(cnt) : "memory");
}
__device__ __forceinline__ void fence_proxy_async_cta() {
    asm volatile("fence.proxy.async.shared::cta;" ::: "memory");
}
__device__ __forceinline__ void mbar_expect_tx(uint32_t mbar, uint32_t bytes) {
    asm volatile("mbarrier.arrive.expect_tx.shared.b64 _, [%0], %1;"
                 :: "r"(mbar), "r"(bytes) : "memory");
}
__device__ __forceinline__ void mbar_arrive(uint32_t mbar) {
    asm volatile("mbarrier.arrive.shared.b64 _, [%0];" :: "r"(mbar) : "memory");
}
__device__ __forceinline__ void mbar_wait(uint32_t mbar, uint32_t parity) {
    asm volatile(
        "{\n\t.reg .pred P;\n"
        "W%=:\n\t"
        "mbarrier.try_wait.parity.acquire.cta.shared::cta.b64 P, [%0], %1, 0x989680;\n\t"
        "@!P bra W%=;\n\t}"
        :: "r"(mbar), "r"(parity) : "memory");
}
__device__ __forceinline__ void tma2d(uint32_t smem, const void* map,
                                      int c0, int c1, uint32_t mbar) {
    asm volatile(
        "cp.async.bulk.tensor.2d.shared::cta.global.tile.mbarrier::complete_tx::bytes "
        "[%0], [%1, {%2, %3}], [%4];"
        :: "r"(smem), "l"(map), "r"(c0), "r"(c1), "r"(mbar) : "memory");
}

// ---------------------------------------------------------------------------
// Merged prep: blocks [0,8192) transpose/convert x (cp.async 3-buffer pipe);
//              blocks [8192,9216) do w (pre-scaled by 1/sqrt(512)).
// ---------------------------------------------------------------------------
__global__ void __launch_bounds__(256)
prep_all(const float* __restrict__ x,
         const float* __restrict__ w0, const float* __restrict__ w1,
         const float* __restrict__ w2, const float* __restrict__ w3)
{
    __shared__ float sx[3][3584];              // 42 KB: one buffer per segment
    const int tid = threadIdx.x;
    const float SC = 0.044194173824159216f;    // 1/sqrt(512)

    if (blockIdx.x >= 8192) {
        // ---- w prep: 1024 blocks, 32x32 transpose tiles, scale folded ----
        const int wb = blockIdx.x - 8192;
        const int bz = wb >> 8, bx = wb & 15, by = (wb >> 4) & 15;
        const float* w = (bz == 0) ? w0 : (bz == 1) ? w1 : (bz == 2) ? w2 : w3;
        const int v0 = bx * 32, u0 = by * 32;
        const int tx = tid & 31, ty = tid >> 5;
        float (*t)[33] = (float(*)[33])sx;

        for (int uu = ty; uu < 32; uu += 8)
            t[uu][tx] = w[(size_t)(u0 + uu) * 512 + v0 + tx];
        __syncthreads();

        const size_t segb = (size_t)bz * 262144;
        for (int vv = ty; vv < 32; vv += 8)
            g_w[segb + (size_t)(v0 + vv) * 512 + u0 + tx] =
                __float2half_rn(t[tx][vv] * SC);
        return;
    }

    // ---- x prep ----
    const int n = blockIdx.x;
    const uint32_t smb = smem_u32(sx);

    // issue ALL three segment loads up-front (separate commit groups)
    #pragma unroll
    for (int s = 1; s < 4; ++s) {
        const int d   = (s == 1) ? 3 : (s == 2) ? 5 : 7;
        const int off = (s == 1) ? 512 : (s == 2) ? 2048 : 4608;
        const int nc  = 512 * d / 4;                     // 16B chunks
        const float* src = x + (size_t)n * TOT + off;
        const uint32_t dst = smb + (s - 1) * 14336;
        for (int c = tid; c < nc; c += 256)
            cpa16(dst + c * 16, src + c * 4);
        cpcommit();
    }

    // D=1 fast path: no transpose, direct float2 -> half2 (overlaps cp.async)
    {
        const float2 v = ((const float2*)(x + (size_t)n * TOT))[tid];
        __half2 p; p.x = __float2half_rn(v.x); p.y = __float2half_rn(v.y);
        ((__half2*)&g_xT[(size_t)n * 512])[tid] = p;
    }

    #pragma unroll
    for (int s = 1; s < 4; ++s) {
        const int d  = (s == 1) ? 3 : (s == 2) ? 5 : 7;
        const int rb = (s == 1) ? 8192 : (s == 2) ? 32768 : 73728;
        const int nf = 512 * d;
        if (s == 1) cpwait<2>(); else if (s == 2) cpwait<1>(); else cpwait<0>();
        __syncthreads();

        const float* sb = sx[s - 1];
        for (int e2 = tid; e2 < nf / 2; e2 += 256) {
            const int e = 2 * e2;
            const int u = e & 511;          // e = i*512 + u
            const int i = e >> 9;
            __half2 p;
            p.x = __float2half_rn(sb[u * d + i]);
            p.y = __float2half_rn(sb[(u + 1) * d + i]);
            *(__half2*)&g_xT[((size_t)rb + (size_t)n * d + i) * 512 + u] = p;
        }
        // no trailing sync needed: each segment has its own buffer
    }
}

// ---------------------------------------------------------------------------
// Main GEMM body (mma.sync fp16, TMA 3-stage pipeline, no syncthreads in loop)
//   C[m=(n,i)][v] = sum_u X[m][u] * Wsc[v][u];  (scale pre-folded into W)
// CTA tile 128x128, warp tile 64x32, BK=64, 2 CTAs/SM (16 warps/SM).
// ---------------------------------------------------------------------------
constexpr int STAGE    = 32768;              // X 16K + W 16K
constexpr int MBAR_OFF = 3 * STAGE;          // 98304
constexpr int SMEM_DYN = MBAR_OFF + 48;      // + 3 full + 3 empty mbars

template<int SEG, int D, int OFF, int ROWBASE>
__device__ __forceinline__ void gemm_body(float* __restrict__ out, int lb, char* sm,
                                          const CUtensorMap* tmX, const CUtensorMap* tmW)
{
    const int tid  = threadIdx.x;
    const int lane = tid & 31;
    const int wid  = tid >> 5;
    const int vb   = (lb & 3) * 128;       // v-tile base (fast -> L2 X reuse)
    const int mb   = (lb >> 2) * 128;      // m-tile base
    const int wm   = (wid & 1) * 64;       // warp M offset (2x4 warp grid)
    const int wn   = (wid >> 1) * 32;      // warp N offset
    const uint32_t smb = smem_u32(sm);
    const uint32_t mbF = smb + MBAR_OFF;       // full[3]
    const uint32_t mbE = smb + MBAR_OFF + 24;  // empty[3]

    if (tid == 0) {
        #pragma unroll
        for (int b = 0; b < 3; ++b) {
            mbar_init(mbF + b * 8, 1);     // completed by expect_tx + TMA tx
            mbar_init(mbE + b * 8, 8);     // one arrive per warp
        }
        fence_proxy_async_cta();           // init visible to async (TMA) proxy
    }
    __syncthreads();

    // producer: chunk j -> buffer j%3.  empty parity: ((j/3)&1)^1 (first pass free)
    auto produce = [&](int j, int buf, uint32_t epar) {
        const uint32_t fm = mbF + buf * 8;
        mbar_wait(mbE + buf * 8, epar);
        mbar_expect_tx(fm, 2 * 16384);
        tma2d(smb + buf * STAGE,         tmX, j * 64, ROWBASE + mb,  fm);
        tma2d(smb + buf * STAGE + 16384, tmW, j * 64, SEG * 512 + vb, fm);
    };

    float acc[4][4][4] = {};

    // ldmatrix lane addressing.  Bits 5-6 of the pre-swizzle bases are zero
    // (row*128 >= bit7, kb in {0,16}) and the SW128 XOR pattern depends only
    // on bits 7-9, so XOR-ing ks*32 onto any held address whose low bits come
    // solely from the swizzled base is exact:  addr ^ (ks*32).
    const int a_m  = (lane & 7) + ((lane >> 3) & 1) * 8;
    const int a_kb = ((lane >> 4) & 1) * 16;
    const int b_n  = (lane & 7) + ((lane >> 4) & 1) * 8;
    const int b_kb = ((lane >> 3) & 1) * 16;
    const uint32_t aSwz = swz((uint32_t)((wm + a_m) * 128 + a_kb));
    const uint32_t bSwz = swz((uint32_t)((wn + b_n) * 128 + b_kb));

    auto compute = [&](int buf) {
        const uint32_t xA = smb + buf * STAGE + aSwz;
        const uint32_t wA = smb + buf * STAGE + 16384 + bSwz;
        #pragma unroll
        for (int ks = 0; ks < 4; ++ks) {
            const uint32_t kx = (uint32_t)(ks * 32);
            uint32_t a[4][4], b[2][4];
            #pragma unroll
            for (int mk = 0; mk < 4; ++mk) ldmx4(a[mk], (xA + mk * 2048) ^ kx);
            #pragma unroll
            for (int nh = 0; nh < 2; ++nh) ldmx4(b[nh], (wA + nh * 2048) ^ kx);
            #pragma unroll
            for (int mk = 0; mk < 4; ++mk)
                #pragma unroll
                for (int nb = 0; nb < 4; ++nb)
                    mma16816(acc[mk][nb], a[mk],
                             b[nb >> 1][(nb & 1) * 2], b[nb >> 1][(nb & 1) * 2 + 1]);
        }
    };

    if (tid == 0) { produce(0, 0, 1); produce(1, 1, 1); }

    // incremental ring counters (no div/mod in the loop)
    int cbuf = 0, cpar = 0;                 // consumer: buffer, full-parity
    int pbuf = 2, ppar = 1;                 // producer: buffer, empty-parity
    #pragma unroll 1
    for (int k = 0; k < 8; ++k) {
        if (tid == 0 && k < 6) {
            produce(k + 2, pbuf, ppar);
            if (++pbuf == 3) { pbuf = 0; ppar ^= 1; }
        }
        mbar_wait(mbF + cbuf * 8, cpar);    // acquire: TMA data -> ldmatrix
        compute(cbuf);
        if (lane == 0) mbar_arrive(mbE + cbuf * 8);   // warp's LDSM reads done
        if (++cbuf == 3) { cbuf = 0; cpar ^= 1; }
    }

    // ---- epilogue: acc -> smem [m][v] (stride 132) -> contiguous stores ----
    __syncthreads();                       // all compute done before smem reuse
    float* so = (float*)sm;
    #pragma unroll
    for (int mk = 0; mk < 4; ++mk)
        #pragma unroll
        for (int nb = 0; nb < 4; ++nb) {
            const int row = wm + mk * 16 + (lane >> 2);
            const int col = wn + nb * 8 + (lane & 3) * 2;
            float2 v0 = make_float2(acc[mk][nb][0], acc[mk][nb][1]);
            float2 v1 = make_float2(acc[mk][nb][2], acc[mk][nb][3]);
            *(float2*)&so[row * 132 + col]       = v0;
            *(float2*)&so[(row + 8) * 132 + col] = v1;
        }
    __syncthreads();

    constexpr int SPAN = 128 * D;              // contiguous out floats per n
    const int n0 = mb / D;

    if (D == 1) {
        // float4 stores: 128 rows x 32 float4
        for (int t4 = tid; t4 < 128 * 32; t4 += 256) {
            const int ni = t4 >> 5;
            const int v4 = (t4 & 31) * 4;
            const float* r = &so[ni * 132 + v4];
            float4 v = make_float4(r[0], r[1], r[2], r[3]);
            *(float4*)&out[(size_t)(n0 + ni) * TOT + OFF + vb + v4] = v;
        }
        return;
    }

    // division-free epilogue for D in {3,5,7}
    const int base = n0 * D - mb;              // in (-D, 0]
    const int n1 = (mb + 127) / D;
    const int total = (n1 - n0 + 1) * SPAN;
    constexpr int QD = 256 / D, RD = 256 % D;

    int ni = 0;                                // tid < 256 <= SPAN for D>=3
    int jj = tid;
    int vl = jj / D;                           // once, const-div
    int ii = jj - vl * D;

    for (int t = tid; t < total; t += 256) {
        const int mm = ni * D + ii + base;     // m - mb
        if (mm >= 0 && mm < 128)
            out[(size_t)(n0 + ni) * TOT + OFF + (size_t)vb * D + jj] =
                so[mm * 132 + vl];
        jj += 256; vl += QD; ii += RD;
        if (ii >= D)    { ii -= D;    vl += 1; }
        if (jj >= SPAN) { jj -= SPAN; vl -= 128; ni += 1; }
    }
}

// Merged kernel: all 4 segments in one launch (single tail wave).
// seg CTA counts: 256 / 768 / 1280 / 1792  (total 4096)
__global__ void __launch_bounds__(256, 2)
gemm_all(float* __restrict__ out,
         const __grid_constant__ CUtensorMap tmX,
         const __grid_constant__ CUtensorMap tmW)
{
    extern __shared__ __align__(1024) char sm[];
    const int bid = blockIdx.x;
    if      (bid < 256)  gemm_body<0, 1, 0,    0>    (out, bid,        sm, &tmX, &tmW);
    else if (bid < 1024) gemm_body<1, 3, 512,  8192> (out, bid - 256,  sm, &tmX, &tmW);
    else if (bid < 2304) gemm_body<2, 5, 2048, 32768>(out, bid - 1024, sm, &tmX, &tmW);
    else                 gemm_body<3, 7, 4608, 73728>(out, bid - 2304, sm, &tmX, &tmW);
}

// ---------------------------------------------------------------------------
// host: tensormap construction (driver entry point; no -lcuda needed)
// ---------------------------------------------------------------------------
typedef CUresult (*EncodeFn)(CUtensorMap*, CUtensorMapDataType, cuuint32_t, void*,
                             const cuuint64_t*, const cuuint64_t*, const cuuint32_t*,
                             const cuuint32_t*, CUtensorMapInterleave, CUtensorMapSwizzle,
                             CUtensorMapL2promotion, CUtensorMapFloatOOBfill);

static EncodeFn get_encode_fn() {
    static EncodeFn fn = nullptr;
    if (!fn) {
        void* p = nullptr;
        cudaDriverEntryPointQueryResult st;
        cudaGetDriverEntryPoint("cuTensorMapEncodeTiled", &p, cudaEnableDefault, &st);
        fn = (EncodeFn)p;
    }
    return fn;
}

extern "C" void kernel_launch(void* const* d_in, const int* in_sizes, int n_in,
                              void* d_out, int out_size)
{
    const float* x  = (const float*)d_in[0];
    const float* w0 = (const float*)d_in[1];
    const float* w1 = (const float*)d_in[2];
    const float* w2 = (const float*)d_in[3];
    const float* w3 = (const float*)d_in[4];
    float* out = (float*)d_out;

    // tensormaps over the fixed __device__ scratch (stable across graph replays)
    CUtensorMap tmX{}, tmW{};
    {
        void *pX = nullptr, *pW = nullptr;
        cudaGetSymbolAddress(&pX, g_xT);
        cudaGetSymbolAddress(&pW, g_w);
        EncodeFn enc = get_encode_fn();
        cuuint64_t dimX[2] = {512, (cuuint64_t)ROWS_TOTAL};
        cuuint64_t dimW[2] = {512, 2048};
        cuuint64_t strB[1] = {1024};                     // row stride bytes
        cuuint32_t box[2]  = {64, 128};
        cuuint32_t es[2]   = {1, 1};
        enc(&tmX, CU_TENSOR_MAP_DATA_TYPE_FLOAT16, 2, pX, dimX, strB, box, es,
            CU_TENSOR_MAP_INTERLEAVE_NONE, CU_TENSOR_MAP_SWIZZLE_128B,
            CU_TENSOR_MAP_L2_PROMOTION_L2_128B, CU_TENSOR_MAP_FLOAT_OOB_FILL_NONE);
        enc(&tmW, CU_TENSOR_MAP_DATA_TYPE_FLOAT16, 2, pW, dimW, strB, box, es,
            CU_TENSOR_MAP_INTERLEAVE_NONE, CU_TENSOR_MAP_SWIZZLE_128B,
            CU_TENSOR_MAP_L2_PROMOTION_L2_128B, CU_TENSOR_MAP_FLOAT_OOB_FILL_NONE);
    }

    cudaFuncSetAttribute(gemm_all, cudaFuncAttributeMaxDynamicSharedMemorySize, SMEM_DYN);

    prep_all<<<9216, 256>>>(x, w0, w1, w2, w3);
    gemm_all<<<4096, 256, SMEM_DYN>>>(out, tmX, tmW);
}